// round 16
// baseline (speedup 1.0000x reference)
#include <cuda_runtime.h>
#include <cuda_bf16.h>
#include <cstdint>

#define TSEQ  512
#define BATCH 64
#define EMBD  512
#define HIDD  1024
#define G4    4096

#define STRD  144            // image row bytes: 64 bf16 + 8 pad (conflict-free ldmatrix)
#define CHB   9216           // chunk bytes = 64 rows * 144
#define NCHUNK 16            // step K = 1024 = 16 * 64
#define NCX    8             // xproj K = 512 = 8 * 64

// ---- step kernel smem map: 4-slot ring + 2 pair-mbarriers -------------------
#define ST(s, w)  ((s) * 36864 + (w) * CHB)    // w: 0=Ahi 1=Alo 2=Bhi 3=Blo
#define SM_MBAR   147456                        // two 8-byte mbarriers
#define SMEM_STEP 147712

// ---- xproj kernel smem map (2-stage ring) -----------------------------------
#define STX(s, w) ((s) * 36864 + (w) * CHB)
#define SMX_GT    73728
#define SMX_IDX   91136
#define SMEM_X    91648

// ---------------- device scratch --------------------------------------------
__device__ float g_xp[(size_t)2 * TSEQ * G4 * BATCH];            // permuted [d][t][mt][prow][b]
__device__ float g_hist[(size_t)2 * TSEQ * HIDD * BATCH];
// Whh image: [d][hl][mt64][chunk16][64 rows][144B]
__device__ __align__(128) unsigned char g_Wt[(size_t)2 * 2 * 64 * NCHUNK * CHB];
// Wih image: [d][hl][gt64][chunk8][64 rows][144B]
__device__ __align__(128) unsigned char g_WihT[(size_t)2 * 2 * 64 * NCX * CHB];
// embedding table bf16 hi/lo
__device__ __align__(128) __nv_bfloat16 g_Ehi[(size_t)32000 * EMBD];
__device__ __align__(128) __nv_bfloat16 g_Elo[(size_t)32000 * EMBD];
// h image: [d][pp][hl][chunk16][64 k][144B]
__device__ __align__(128) unsigned char g_hT[(size_t)2 * 2 * 2 * NCHUNK * CHB];
// cell state [d][mt][u16][b64]
__device__ float g_c[2 * 64 * 16 * 64];

// ---------------- helpers ----------------------------------------------------
typedef unsigned long long u64;
__device__ __forceinline__ float sigmoidf_(float x) { return 1.0f / (1.0f + expf(-x)); }

__device__ __forceinline__ uint32_t smem_u32(const void* p) {
    uint32_t a;
    asm("{ .reg .u64 t; cvta.to.shared.u64 t, %1; cvt.u32.u64 %0, t; }" : "=r"(a) : "l"(p));
    return a;
}
__device__ __forceinline__ void cp16(uint32_t dst, const void* src) {
    asm volatile("cp.async.cg.shared.global [%0], [%1], 16;" :: "r"(dst), "l"(src));
}
__device__ __forceinline__ void cp_commit() { asm volatile("cp.async.commit_group;"); }
template<int N> __device__ __forceinline__ void cp_wait() {
    asm volatile("cp.async.wait_group %0;" :: "n"(N));
}
__device__ __forceinline__ void mbar_init(uint32_t a, uint32_t n) {
    asm volatile("mbarrier.init.shared.b64 [%0], %1;" :: "r"(a), "r"(n) : "memory");
}
__device__ __forceinline__ void mbar_expect(uint32_t a, uint32_t bytes) {
    asm volatile("mbarrier.arrive.expect_tx.shared.b64 _, [%0], %1;" :: "r"(a), "r"(bytes) : "memory");
}
__device__ __forceinline__ void mbar_wait(uint32_t a, uint32_t ph) {
    uint32_t done;
    asm volatile("{\n\t.reg .pred p;\n\t"
        "mbarrier.try_wait.parity.acquire.cta.shared::cta.b64 p, [%1], %2;\n\t"
        "selp.b32 %0, 1, 0, p;\n\t}"
        : "=r"(done) : "r"(a), "r"(ph) : "memory");
    if (!done) {
        asm volatile("{\n\t.reg .pred P1;\n\t"
            "WL_%=:\n\t"
            "mbarrier.try_wait.parity.acquire.cta.shared::cta.b64 P1, [%0], %1, 0x989680;\n\t"
            "@P1 bra.uni WD_%=;\n\t"
            "bra.uni WL_%=;\n\t"
            "WD_%=:\n\t}" :: "r"(a), "r"(ph) : "memory");
    }
}
__device__ __forceinline__ void bulkcp(uint32_t dst, const void* src, uint32_t bytes, uint32_t mbar) {
    asm volatile("cp.async.bulk.shared::cluster.global.mbarrier::complete_tx::bytes [%0], [%1], %2, [%3];"
        :: "r"(dst), "l"(src), "r"(bytes), "r"(mbar) : "memory");
}
__device__ __forceinline__ void ldm4(uint32_t* r, uint32_t a) {
    asm volatile("ldmatrix.sync.aligned.m8n8.x4.shared.b16 {%0,%1,%2,%3}, [%4];"
        : "=r"(r[0]), "=r"(r[1]), "=r"(r[2]), "=r"(r[3]) : "r"(a));
}
__device__ __forceinline__ void ldm4t(uint32_t* r, uint32_t a) {
    asm volatile("ldmatrix.sync.aligned.m8n8.x4.trans.shared.b16 {%0,%1,%2,%3}, [%4];"
        : "=r"(r[0]), "=r"(r[1]), "=r"(r[2]), "=r"(r[3]) : "r"(a));
}
__device__ __forceinline__ void mma16816(float* c, const uint32_t* a, uint32_t b0, uint32_t b1) {
    asm volatile("mma.sync.aligned.m16n8k16.row.col.f32.bf16.bf16.f32 "
        "{%0,%1,%2,%3}, {%4,%5,%6,%7}, {%8,%9}, {%0,%1,%2,%3};"
        : "+f"(c[0]), "+f"(c[1]), "+f"(c[2]), "+f"(c[3])
        : "r"(a[0]), "r"(a[1]), "r"(a[2]), "r"(a[3]), "r"(b0), "r"(b1));
}

// ---------------- init: zero h image + cell state ----------------------------
__global__ void init_kernel() {
    size_t idx = (size_t)blockIdx.x * 1024 + threadIdx.x;
    if (idx < sizeof(g_hT) / 4) ((unsigned*)g_hT)[idx] = 0u;
    if (idx < (size_t)2 * 64 * 16 * 64) g_c[idx] = 0.0f;
}

// ---------------- merged prep: Whh + Wih images + embedding ------------------
// grid.x: [0,8192) Whh rows, [8192,16384) Wih rows, [16384,48384) emb rows
__global__ __launch_bounds__(256) void prep_all(
    const float* __restrict__ Whh_f, const float* __restrict__ Whh_b,
    const float* __restrict__ Wih_f, const float* __restrict__ Wih_b,
    const float* __restrict__ emb)
{
    const int bx = blockIdx.x;
    if (bx < 8192) {
        const int d  = bx >> 12;
        const int rr = bx & 4095;
        const float* W = d ? Whh_b : Whh_f;
        const int v = rr >> 10, u = rr & 1023;
        const int mt = u >> 4;
        const int prow = v * 16 + (u & 15);
        const size_t base_hi = (((size_t)(d * 2 + 0) * 64 + mt) * NCHUNK) * CHB;
        const size_t base_lo = (((size_t)(d * 2 + 1) * 64 + mt) * NCHUNK) * CHB;
        for (int k = threadIdx.x; k < HIDD; k += 256) {
            float w = W[(size_t)rr * HIDD + k];
            __nv_bfloat16 hi = __float2bfloat16(w);
            __nv_bfloat16 lo = __float2bfloat16(w - __bfloat162float(hi));
            int c = k >> 6, kl = k & 63;
            size_t off = (size_t)c * CHB + (size_t)prow * STRD + kl * 2;
            *(__nv_bfloat16*)(g_Wt + base_hi + off) = hi;
            *(__nv_bfloat16*)(g_Wt + base_lo + off) = lo;
        }
    } else if (bx < 16384) {
        const int bb = bx - 8192;
        const int d  = bb >> 12;
        const int rr = bb & 4095;
        const float* W = d ? Wih_b : Wih_f;
        const int gt = rr >> 6, r = rr & 63;
        const size_t base_hi = (((size_t)(d * 2 + 0) * 64 + gt) * NCX) * CHB;
        const size_t base_lo = (((size_t)(d * 2 + 1) * 64 + gt) * NCX) * CHB;
        for (int k = threadIdx.x; k < EMBD; k += 256) {
            float w = W[(size_t)rr * EMBD + k];
            __nv_bfloat16 hi = __float2bfloat16(w);
            __nv_bfloat16 lo = __float2bfloat16(w - __bfloat162float(hi));
            int c = k >> 6, kl = k & 63;
            size_t off = (size_t)c * CHB + (size_t)r * STRD + kl * 2;
            *(__nv_bfloat16*)(g_WihT + base_hi + off) = hi;
            *(__nv_bfloat16*)(g_WihT + base_lo + off) = lo;
        }
    } else {
        const int v = bx - 16384;
        const size_t base = (size_t)v * EMBD;
#pragma unroll
        for (int s = 0; s < 2; ++s) {
            int k = threadIdx.x + s * 256;
            float x = (v == 0) ? 0.0f : emb[base + k];
            __nv_bfloat16 hi = __float2bfloat16(x);
            g_Ehi[base + k] = hi;
            g_Elo[base + k] = __float2bfloat16(x - __bfloat162float(hi));
        }
    }
}

// ---------------- xproj via HMMA: xp = Wih * embed(src) + biases -------------
// grid (gt=64, t=512, d=2), 256 thr = 8 warps (4M x 2N), warp tile 16x32, K=512
__global__ __launch_bounds__(256, 2) void xproj_mma(
    const int* __restrict__ src,
    const float* __restrict__ bih_f, const float* __restrict__ bhh_f,
    const float* __restrict__ bih_b, const float* __restrict__ bhh_b)
{
    extern __shared__ __align__(16) unsigned char smem[];
    const uint32_t sb = smem_u32(smem);

    const int tid  = threadIdx.x;
    const int wid  = tid >> 5;
    const int lane = tid & 31;
    const int gt   = blockIdx.x;
    const int t    = blockIdx.y;
    const int d    = blockIdx.z;

    int* sIdx = (int*)(smem + SMX_IDX);
    if (tid < 64) sIdx[tid] = src[(d ? (TSEQ - 1 - t) : t) * BATCH + tid];
    __syncthreads();

    const unsigned char* srcA0 = g_WihT + (((size_t)(d * 2 + 0) * 64 + gt) * NCX) * CHB;
    const unsigned char* srcA1 = g_WihT + (((size_t)(d * 2 + 1) * 64 + gt) * NCX) * CHB;

    auto stage = [&](int c, int s) {
        const size_t cb = (size_t)c * CHB;
        for (int i = tid; i < 1152; i += 256) {
            int w = i / 576, off = (i - w * 576) * 16;
            cp16(sb + STX(s, w) + off, (w ? srcA1 : srcA0) + cb + off);
        }
        for (int i = tid; i < 1024; i += 256) {
            int hl = i >> 9, r = i & 511;
            int b = r >> 3, q = r & 7;
            const __nv_bfloat16* ep = (hl ? g_Elo : g_Ehi)
                + (size_t)sIdx[b] * EMBD + c * 64 + q * 8;
            cp16(sb + STX(s, 2 + hl) + b * STRD + q * 16, ep);
        }
    };

    stage(0, 0); cp_commit();
    stage(1, 1); cp_commit();

    const int wm = wid & 3;
    const int wn = wid >> 2;
    const int ti = lane >> 3, li = lane & 7;
    const uint32_t aoff = (uint32_t)((wm * 16 + (ti & 1) * 8 + li) * STRD + (ti >> 1) * 16);
    const uint32_t boff = (uint32_t)((wn * 32 + lane) * STRD);

    float acc[4][4];
#pragma unroll
    for (int q = 0; q < 4; ++q)
#pragma unroll
        for (int l = 0; l < 4; ++l) acc[q][l] = 0.0f;

#pragma unroll 1
    for (int c = 0; c < NCX; ++c) {
        if (c + 1 < NCX) {
            if (c > 0) { stage(c + 1, (c + 1) & 1); cp_commit(); }
            cp_wait<1>();
        } else {
            cp_wait<0>();
        }
        __syncthreads();
        const uint32_t A_hi = sb + STX(c & 1, 0);
        const uint32_t A_lo = sb + STX(c & 1, 1);
        const uint32_t B_hi = sb + STX(c & 1, 2);
        const uint32_t B_lo = sb + STX(c & 1, 3);
#pragma unroll
        for (int kk = 0; kk < 4; ++kk) {
            uint32_t ahi[4], alo[4], b0h[4], b1h[4], b0l[4], b1l[4];
            ldm4(ahi, A_hi + aoff + kk * 32);
            ldm4(alo, A_lo + aoff + kk * 32);
            ldm4(b0h, B_hi + boff + kk * 32);
            ldm4(b1h, B_hi + boff + kk * 32 + 16);
            ldm4(b0l, B_lo + boff + kk * 32);
            ldm4(b1l, B_lo + boff + kk * 32 + 16);
#pragma unroll
            for (int q = 0; q < 4; ++q) mma16816(acc[q], ahi, b0h[q], b1h[q]);
#pragma unroll
            for (int q = 0; q < 4; ++q) mma16816(acc[q], alo, b0h[q], b1h[q]);
#pragma unroll
            for (int q = 0; q < 4; ++q) mma16816(acc[q], ahi, b0l[q], b1l[q]);
        }
        __syncthreads();
    }

    // write accs to smem gates (stride 68 f32)
    float* sg = (float*)(smem + SMX_GT);
    {
        const int dr = lane >> 2, dc = (lane & 3) * 2;
#pragma unroll
        for (int q = 0; q < 4; ++q) {
            const int col = wn * 32 + q * 8 + dc;
            *(float2*)&sg[(wm * 16 + dr)     * 68 + col] = make_float2(acc[q][0], acc[q][1]);
            *(float2*)&sg[(wm * 16 + dr + 8) * 68 + col] = make_float2(acc[q][2], acc[q][3]);
        }
    }
    __syncthreads();

    // bias + permuted scatter to g_xp (streaming stores)
    {
        const float* bih = d ? bih_b : bih_f;
        const float* bhh = d ? bhh_b : bhh_f;
        const int r = tid >> 2, jj = tid & 3;
        const int gr = gt * 64 + r;
        const float bias = bih[gr] + bhh[gr];
        const int v = gr >> 10, u = gr & 1023;
        const int mt = u >> 4, prow = v * 16 + (u & 15);
        float* dst = g_xp + (((size_t)(d * TSEQ + t) * 64 + mt) * 64 + prow) * 64 + jj * 16;
#pragma unroll
        for (int p = 0; p < 4; ++p) {
            float4 o = *(float4*)&sg[r * 68 + jj * 16 + p * 4];
            o.x += bias; o.y += bias; o.z += bias; o.w += bias;
            __stcs((float4*)(dst + p * 4), o);
        }
    }
}

// ---------------- one recurrent step: HMMA GEMM + fused pointwise ------------
// grid (64, 2): mt, d.  512 threads = 16 warps (4M x 4N), warp tile 16x16.
// Staging via cp.async.bulk + mbarrier (elected thread). 4-slot ring, chunks
// in pairs, one __syncthreads per pair. xp in registers; gates alias slot 0.
__global__ __launch_bounds__(512) void step_mma(int t)
{
    extern __shared__ __align__(16) unsigned char smem[];
    const uint32_t sb = smem_u32(smem);

    const int tid  = threadIdx.x;
    const int wid  = tid >> 5;
    const int lane = tid & 31;
    const int mt   = blockIdx.x;
    const int d    = blockIdx.y;
    const int pp   = t & 1;

    const unsigned char* srcA_hi = g_Wt + (((size_t)(d * 2 + 0) * 64 + mt) * NCHUNK) * CHB;
    const unsigned char* srcA_lo = g_Wt + (((size_t)(d * 2 + 1) * 64 + mt) * NCHUNK) * CHB;
    const unsigned char* srcB_hi = g_hT + (((size_t)(d * 2 + pp) * 2 + 0) * NCHUNK) * CHB;
    const unsigned char* srcB_lo = g_hT + (((size_t)(d * 2 + pp) * 2 + 1) * NCHUNK) * CHB;

    const uint32_t mb[2] = { sb + SM_MBAR, sb + SM_MBAR + 8 };

    // stage chunk-pair (c0, c0+1) into slots c0&3, (c0+1)&3, completing mbar
    auto stage_pair = [&](int c0, uint32_t mbar) {
        mbar_expect(mbar, 2 * 4 * CHB);
#pragma unroll
        for (int cc = c0; cc < c0 + 2; ++cc) {
            const int s = cc & 3;
            const size_t cb = (size_t)cc * CHB;
            bulkcp(sb + ST(s, 0), srcA_hi + cb, CHB, mbar);
            bulkcp(sb + ST(s, 1), srcA_lo + cb, CHB, mbar);
            bulkcp(sb + ST(s, 2), srcB_hi + cb, CHB, mbar);
            bulkcp(sb + ST(s, 3), srcB_lo + cb, CHB, mbar);
        }
    };

    if (tid == 0) {
        mbar_init(mb[0], 1);
        mbar_init(mb[1], 1);
    }
    __syncthreads();
    if (tid == 0) {
        stage_pair(0, mb[0]);   // chunks 0,1 -> slots 0,1
        stage_pair(2, mb[1]);   // chunks 2,3 -> slots 2,3
    }

    // xp slice into registers (first 256 threads; latency hidden by staging)
    const int u  = tid >> 4;             // (tid<256) 0..15
    const int b0 = (tid & 15) * 4;
    float4 xv[4];
    if (tid < 256) {
        const float* xps = g_xp + (((size_t)(d * TSEQ + t) * 64 + mt) * 64) * 64;
#pragma unroll
        for (int v = 0; v < 4; ++v)
            xv[v] = __ldg((const float4*)(xps + (v * 16 + u) * 64 + b0));
    }

    const int wm = wid & 3;                  // M group (16 rows)
    const int wn = wid >> 2;                 // N group (16 cols)
    const int ti = lane >> 3, li = lane & 7;
    const uint32_t aoff  = (uint32_t)((wm * 16 + (ti & 1) * 8 + li) * STRD + (ti >> 1) * 16);
    const uint32_t boffA = (uint32_t)(((ti >> 1) * 8 + li) * STRD + (wn * 16 + (ti & 1) * 8) * 2);

    float acc[2][4];
#pragma unroll
    for (int q = 0; q < 2; ++q)
#pragma unroll
        for (int l = 0; l < 4; ++l) acc[q][l] = 0.0f;

#pragma unroll 1
    for (int p = 0; p < 8; ++p) {
        // wait pair p's data (chunks 2p, 2p+1)
        mbar_wait(mb[p & 1], (p >> 1) & 1);
#pragma unroll
        for (int h = 0; h < 2; ++h) {
            const int s = (2 * p + h) & 3;
            const uint32_t A_hi = sb + ST(s, 0);
            const uint32_t A_lo = sb + ST(s, 1);
            const uint32_t B_hi = sb + ST(s, 2);
            const uint32_t B_lo = sb + ST(s, 3);
#pragma unroll
            for (int kk = 0; kk < 4; ++kk) {
                uint32_t ahi[4], alo[4], bh[4], bl[4];
                ldm4(ahi, A_hi + aoff + kk * 32);
                ldm4(alo, A_lo + aoff + kk * 32);
                ldm4t(bh, B_hi + boffA + kk * 16 * STRD);
                ldm4t(bl, B_lo + boffA + kk * 16 * STRD);
                mma16816(acc[0], ahi, bh[0], bh[2]);
                mma16816(acc[1], ahi, bh[1], bh[3]);
                mma16816(acc[0], alo, bh[0], bh[2]);
                mma16816(acc[1], alo, bh[1], bh[3]);
                mma16816(acc[0], ahi, bl[0], bl[2]);
                mma16816(acc[1], ahi, bl[1], bl[3]);
            }
        }
        __syncthreads();   // all consumers done with pair p's slots
        if (p < 6 && tid == 0)
            stage_pair(2 * p + 4, mb[p & 1]);   // reuse pair p's slots
    }

    // write accs to smem gates (stride 68 f32) — aliases ring slot 0 (dead)
    float* sg = (float*)smem;
    {
        const int dr = lane >> 2, dc = (lane & 3) * 2;
#pragma unroll
        for (int q = 0; q < 2; ++q) {
            const int col = wn * 16 + q * 8 + dc;
            *(float2*)&sg[(wm * 16 + dr)     * 68 + col] = make_float2(acc[q][0], acc[q][1]);
            *(float2*)&sg[(wm * 16 + dr + 8) * 68 + col] = make_float2(acc[q][2], acc[q][3]);
        }
    }
    __syncthreads();

    // fused pointwise LSTM (first 256 threads; xp from registers)
    if (tid < 256) {
        float gv[4][4];
#pragma unroll
        for (int v = 0; v < 4; ++v) {
            const int r = v * 16 + u;
#pragma unroll
            for (int l = 0; l < 4; ++l)
                gv[v][l] = sg[r * 68 + b0 + l] + ((const float*)&xv[v])[l];
        }
        float* cp = g_c + (((size_t)d * 64 + mt) * 16 + u) * 64 + b0;
        float4 cv = *(float4*)cp;
        float* cl = (float*)&cv;
        float hv[4];
#pragma unroll
        for (int l = 0; l < 4; ++l) {
            float ig = sigmoidf_(gv[0][l]);
            float fg = sigmoidf_(gv[1][l]);
            float gg = tanhf(gv[2][l]);
            float og = sigmoidf_(gv[3][l]);
            float cn = fg * cl[l] + ig * gg;
            cl[l] = cn;
            hv[l] = og * tanhf(cn);
        }
        *(float4*)cp = cv;

        const int t_out = d ? (TSEQ - 1 - t) : t;
        const int ug = mt * 16 + u;
        __stcs((float4*)&g_hist[((size_t)(d * TSEQ + t_out) * HIDD + ug) * BATCH + b0],
               make_float4(hv[0], hv[1], hv[2], hv[3]));

        __nv_bfloat16 ph[4], plo[4];
#pragma unroll
        for (int l = 0; l < 4; ++l) {
            ph[l]  = __float2bfloat16(hv[l]);
            plo[l] = __float2bfloat16(hv[l] - __bfloat162float(ph[l]));
        }
        const int c = ug >> 6, kl = ug & 63;
        const size_t off = (size_t)c * CHB + (size_t)kl * STRD + b0 * 2;
        unsigned char* wb_hi = g_hT + (((size_t)(d * 2 + (pp ^ 1)) * 2 + 0) * NCHUNK) * CHB;
        unsigned char* wb_lo = g_hT + (((size_t)(d * 2 + (pp ^ 1)) * 2 + 1) * NCHUNK) * CHB;
        *(u64*)(wb_hi + off) = *(u64*)ph;
        *(u64*)(wb_lo + off) = *(u64*)plo;
    }
}

// ---------------- combine: out[b][t][h] = hf + hb ---------------------------
__global__ __launch_bounds__(256) void combine_kernel(float* __restrict__ out)
{
    __shared__ float s[128 * 65];
    const int uc  = blockIdx.x;
    const int t   = blockIdx.y;
    const int tid = threadIdx.x;
    const float* hf = g_hist + (size_t)t          * HIDD * BATCH;
    const float* hb = g_hist + (size_t)(TSEQ + t) * HIDD * BATCH;
    for (int x = tid; x < 128 * 64; x += 256) {
        int uu = x >> 6, b = x & 63;
        int u = uc * 128 + uu;
        s[uu * 65 + b] = hf[(size_t)u * BATCH + b] + hb[(size_t)u * BATCH + b];
    }
    __syncthreads();
    for (int x = tid; x < 128 * 64; x += 256) {
        int b = x >> 7, uu = x & 127;
        out[((size_t)b * TSEQ + t) * HIDD + uc * 128 + uu] = s[uu * 65 + b];
    }
}

// ---------------- launch -----------------------------------------------------
extern "C" void kernel_launch(void* const* d_in, const int* in_sizes, int n_in,
                              void* d_out, int out_size)
{
    const int*   src   = (const int*)  d_in[0];
    const float* emb   = (const float*)d_in[1];
    const float* Wih_f = (const float*)d_in[2];
    const float* Whh_f = (const float*)d_in[3];
    const float* bih_f = (const float*)d_in[4];
    const float* bhh_f = (const float*)d_in[5];
    const float* Wih_b = (const float*)d_in[6];
    const float* Whh_b = (const float*)d_in[7];
    const float* bih_b = (const float*)d_in[8];
    const float* bhh_b = (const float*)d_in[9];

    cudaFuncSetAttribute(step_mma, cudaFuncAttributeMaxDynamicSharedMemorySize, SMEM_STEP);
    cudaFuncSetAttribute(xproj_mma, cudaFuncAttributeMaxDynamicSharedMemorySize, SMEM_X);

    init_kernel<<<288, 1024>>>();
    prep_all<<<48384, 256>>>(Whh_f, Whh_b, Wih_f, Wih_b, emb);
    xproj_mma<<<dim3(64, 512, 2), 256, SMEM_X>>>(src, bih_f, bhh_f, bih_b, bhh_b);
    for (int t = 0; t < TSEQ; ++t)
        step_mma<<<dim3(64, 2), 512, SMEM_STEP>>>(t);
    combine_kernel<<<dim3(8, 512), 256>>>((float*)d_out);
}

// round 17
// speedup vs baseline: 1.5469x; 1.5469x over previous
#include <cuda_runtime.h>
#include <cuda_bf16.h>
#include <cstdint>

#define TSEQ  512
#define BATCH 64
#define EMBD  512
#define HIDD  1024
#define G4    4096

#define STRD  144            // image row bytes: 64 bf16 + 8 pad (conflict-free ldmatrix)
#define CHB   9216           // B (h) chunk bytes = 64 k-rows * 144
#define CHA   4608           // A (W) chunk bytes = 32 m-rows * 144
#define NCHUNK 16            // step K = 1024 = 16 * 64
#define NCX    8             // xproj K = 512 = 8 * 64

// ---- step kernel smem map: 4-slot ring (27648 B/slot) + 2 pair-mbarriers ----
#define SLOT      27648
#define OFF_AHI   0
#define OFF_ALO   4608
#define OFF_BHI   9216
#define OFF_BLO   18432
#define SM_MBAR   110592
#define SMEM_STEP 110848     // x2 CTAs = 221696 <= 228KB/SM

// ---- xproj kernel smem map (2-stage ring) -----------------------------------
#define STX(s, w) ((s) * 36864 + (w) * CHB)
#define SMX_GT    73728
#define SMX_IDX   91136
#define SMEM_X    91648

// ---------------- device scratch --------------------------------------------
__device__ float g_xp[(size_t)2 * TSEQ * G4 * BATCH];            // permuted [d][t][mt128][prow32][b]
__device__ float g_hist[(size_t)2 * TSEQ * HIDD * BATCH];
// Whh image: [d][hl][mt128][chunk16][32 rows][144B]
__device__ __align__(128) unsigned char g_Wt[(size_t)2 * 2 * 128 * NCHUNK * CHA];
// Wih image: [d][hl][gt64][chunk8][64 rows][144B]
__device__ __align__(128) unsigned char g_WihT[(size_t)2 * 2 * 64 * NCX * CHB];
// embedding table bf16 hi/lo
__device__ __align__(128) __nv_bfloat16 g_Ehi[(size_t)32000 * EMBD];
__device__ __align__(128) __nv_bfloat16 g_Elo[(size_t)32000 * EMBD];
// h image: [d][pp][hl][chunk16][64 k][144B]
__device__ __align__(128) unsigned char g_hT[(size_t)2 * 2 * 2 * NCHUNK * CHB];
// cell state [d][mt128][u8][b64]
__device__ float g_c[2 * 128 * 8 * 64];

// ---------------- helpers ----------------------------------------------------
typedef unsigned long long u64;
__device__ __forceinline__ float sigmoidf_(float x) { return 1.0f / (1.0f + expf(-x)); }

__device__ __forceinline__ uint32_t smem_u32(const void* p) {
    uint32_t a;
    asm("{ .reg .u64 t; cvta.to.shared.u64 t, %1; cvt.u32.u64 %0, t; }" : "=r"(a) : "l"(p));
    return a;
}
__device__ __forceinline__ void cp16(uint32_t dst, const void* src) {
    asm volatile("cp.async.cg.shared.global [%0], [%1], 16;" :: "r"(dst), "l"(src));
}
__device__ __forceinline__ void cp_commit() { asm volatile("cp.async.commit_group;"); }
template<int N> __device__ __forceinline__ void cp_wait() {
    asm volatile("cp.async.wait_group %0;" :: "n"(N));
}
__device__ __forceinline__ void mbar_init(uint32_t a, uint32_t n) {
    asm volatile("mbarrier.init.shared.b64 [%0], %1;" :: "r"(a), "r"(n) : "memory");
}
__device__ __forceinline__ void mbar_expect(uint32_t a, uint32_t bytes) {
    asm volatile("mbarrier.arrive.expect_tx.shared.b64 _, [%0], %1;" :: "r"(a), "r"(bytes) : "memory");
}
__device__ __forceinline__ void mbar_wait(uint32_t a, uint32_t ph) {
    uint32_t done;
    asm volatile("{\n\t.reg .pred p;\n\t"
        "mbarrier.try_wait.parity.acquire.cta.shared::cta.b64 p, [%1], %2;\n\t"
        "selp.b32 %0, 1, 0, p;\n\t}"
        : "=r"(done) : "r"(a), "r"(ph) : "memory");
    if (!done) {
        asm volatile("{\n\t.reg .pred P1;\n\t"
            "WL_%=:\n\t"
            "mbarrier.try_wait.parity.acquire.cta.shared::cta.b64 P1, [%0], %1, 0x989680;\n\t"
            "@P1 bra.uni WD_%=;\n\t"
            "bra.uni WL_%=;\n\t"
            "WD_%=:\n\t}" :: "r"(a), "r"(ph) : "memory");
    }
}
__device__ __forceinline__ void bulkcp(uint32_t dst, const void* src, uint32_t bytes, uint32_t mbar) {
    asm volatile("cp.async.bulk.shared::cluster.global.mbarrier::complete_tx::bytes [%0], [%1], %2, [%3];"
        :: "r"(dst), "l"(src), "r"(bytes), "r"(mbar) : "memory");
}
__device__ __forceinline__ void ldm4(uint32_t* r, uint32_t a) {
    asm volatile("ldmatrix.sync.aligned.m8n8.x4.shared.b16 {%0,%1,%2,%3}, [%4];"
        : "=r"(r[0]), "=r"(r[1]), "=r"(r[2]), "=r"(r[3]) : "r"(a));
}
__device__ __forceinline__ void ldm4t(uint32_t* r, uint32_t a) {
    asm volatile("ldmatrix.sync.aligned.m8n8.x4.trans.shared.b16 {%0,%1,%2,%3}, [%4];"
        : "=r"(r[0]), "=r"(r[1]), "=r"(r[2]), "=r"(r[3]) : "r"(a));
}
__device__ __forceinline__ void mma16816(float* c, const uint32_t* a, uint32_t b0, uint32_t b1) {
    asm volatile("mma.sync.aligned.m16n8k16.row.col.f32.bf16.bf16.f32 "
        "{%0,%1,%2,%3}, {%4,%5,%6,%7}, {%8,%9}, {%0,%1,%2,%3};"
        : "+f"(c[0]), "+f"(c[1]), "+f"(c[2]), "+f"(c[3])
        : "r"(a[0]), "r"(a[1]), "r"(a[2]), "r"(a[3]), "r"(b0), "r"(b1));
}

// ---------------- init: zero h image + cell state ----------------------------
__global__ void init_kernel() {
    size_t idx = (size_t)blockIdx.x * 1024 + threadIdx.x;
    if (idx < sizeof(g_hT) / 4) ((unsigned*)g_hT)[idx] = 0u;
    if (idx < (size_t)2 * 128 * 8 * 64) g_c[idx] = 0.0f;
}

// ---------------- merged prep: Whh + Wih images + embedding ------------------
// grid.x: [0,8192) Whh rows, [8192,16384) Wih rows, [16384,48384) emb rows
__global__ __launch_bounds__(256) void prep_all(
    const float* __restrict__ Whh_f, const float* __restrict__ Whh_b,
    const float* __restrict__ Wih_f, const float* __restrict__ Wih_b,
    const float* __restrict__ emb)
{
    const int bx = blockIdx.x;
    if (bx < 8192) {
        const int d  = bx >> 12;
        const int rr = bx & 4095;
        const float* W = d ? Whh_b : Whh_f;
        const int v = rr >> 10, u = rr & 1023;
        const int mt = u >> 3;                     // 128 tiles of 8 units
        const int prow = v * 8 + (u & 7);          // 32 rows = 4 gates x 8 units
        const size_t base_hi = (((size_t)(d * 2 + 0) * 128 + mt) * NCHUNK) * CHA;
        const size_t base_lo = (((size_t)(d * 2 + 1) * 128 + mt) * NCHUNK) * CHA;
        for (int k = threadIdx.x; k < HIDD; k += 256) {
            float w = W[(size_t)rr * HIDD + k];
            __nv_bfloat16 hi = __float2bfloat16(w);
            __nv_bfloat16 lo = __float2bfloat16(w - __bfloat162float(hi));
            int c = k >> 6, kl = k & 63;
            size_t off = (size_t)c * CHA + (size_t)prow * STRD + kl * 2;
            *(__nv_bfloat16*)(g_Wt + base_hi + off) = hi;
            *(__nv_bfloat16*)(g_Wt + base_lo + off) = lo;
        }
    } else if (bx < 16384) {
        const int bb = bx - 8192;
        const int d  = bb >> 12;
        const int rr = bb & 4095;
        const float* W = d ? Wih_b : Wih_f;
        const int gt = rr >> 6, r = rr & 63;
        const size_t base_hi = (((size_t)(d * 2 + 0) * 64 + gt) * NCX) * CHB;
        const size_t base_lo = (((size_t)(d * 2 + 1) * 64 + gt) * NCX) * CHB;
        for (int k = threadIdx.x; k < EMBD; k += 256) {
            float w = W[(size_t)rr * EMBD + k];
            __nv_bfloat16 hi = __float2bfloat16(w);
            __nv_bfloat16 lo = __float2bfloat16(w - __bfloat162float(hi));
            int c = k >> 6, kl = k & 63;
            size_t off = (size_t)c * CHB + (size_t)r * STRD + kl * 2;
            *(__nv_bfloat16*)(g_WihT + base_hi + off) = hi;
            *(__nv_bfloat16*)(g_WihT + base_lo + off) = lo;
        }
    } else {
        const int v = bx - 16384;
        const size_t base = (size_t)v * EMBD;
#pragma unroll
        for (int s = 0; s < 2; ++s) {
            int k = threadIdx.x + s * 256;
            float x = (v == 0) ? 0.0f : emb[base + k];
            __nv_bfloat16 hi = __float2bfloat16(x);
            g_Ehi[base + k] = hi;
            g_Elo[base + k] = __float2bfloat16(x - __bfloat162float(hi));
        }
    }
}

// ---------------- xproj via HMMA: xp = Wih * embed(src) + biases -------------
// grid (gt=64, t=512, d=2), 256 thr = 8 warps (4M x 2N), warp tile 16x32, K=512
__global__ __launch_bounds__(256, 2) void xproj_mma(
    const int* __restrict__ src,
    const float* __restrict__ bih_f, const float* __restrict__ bhh_f,
    const float* __restrict__ bih_b, const float* __restrict__ bhh_b)
{
    extern __shared__ __align__(16) unsigned char smem[];
    const uint32_t sb = smem_u32(smem);

    const int tid  = threadIdx.x;
    const int wid  = tid >> 5;
    const int lane = tid & 31;
    const int gt   = blockIdx.x;
    const int t    = blockIdx.y;
    const int d    = blockIdx.z;

    int* sIdx = (int*)(smem + SMX_IDX);
    if (tid < 64) sIdx[tid] = src[(d ? (TSEQ - 1 - t) : t) * BATCH + tid];
    __syncthreads();

    const unsigned char* srcA0 = g_WihT + (((size_t)(d * 2 + 0) * 64 + gt) * NCX) * CHB;
    const unsigned char* srcA1 = g_WihT + (((size_t)(d * 2 + 1) * 64 + gt) * NCX) * CHB;

    auto stage = [&](int c, int s) {
        const size_t cb = (size_t)c * CHB;
        for (int i = tid; i < 1152; i += 256) {
            int w = i / 576, off = (i - w * 576) * 16;
            cp16(sb + STX(s, w) + off, (w ? srcA1 : srcA0) + cb + off);
        }
        for (int i = tid; i < 1024; i += 256) {
            int hl = i >> 9, r = i & 511;
            int b = r >> 3, q = r & 7;
            const __nv_bfloat16* ep = (hl ? g_Elo : g_Ehi)
                + (size_t)sIdx[b] * EMBD + c * 64 + q * 8;
            cp16(sb + STX(s, 2 + hl) + b * STRD + q * 16, ep);
        }
    };

    stage(0, 0); cp_commit();
    stage(1, 1); cp_commit();

    const int wm = wid & 3;
    const int wn = wid >> 2;
    const int ti = lane >> 3, li = lane & 7;
    const uint32_t aoff = (uint32_t)((wm * 16 + (ti & 1) * 8 + li) * STRD + (ti >> 1) * 16);
    const uint32_t boff = (uint32_t)((wn * 32 + lane) * STRD);

    float acc[4][4];
#pragma unroll
    for (int q = 0; q < 4; ++q)
#pragma unroll
        for (int l = 0; l < 4; ++l) acc[q][l] = 0.0f;

#pragma unroll 1
    for (int c = 0; c < NCX; ++c) {
        if (c + 1 < NCX) {
            if (c > 0) { stage(c + 1, (c + 1) & 1); cp_commit(); }
            cp_wait<1>();
        } else {
            cp_wait<0>();
        }
        __syncthreads();
        const uint32_t A_hi = sb + STX(c & 1, 0);
        const uint32_t A_lo = sb + STX(c & 1, 1);
        const uint32_t B_hi = sb + STX(c & 1, 2);
        const uint32_t B_lo = sb + STX(c & 1, 3);
#pragma unroll
        for (int kk = 0; kk < 4; ++kk) {
            uint32_t ahi[4], alo[4], b0h[4], b1h[4], b0l[4], b1l[4];
            ldm4(ahi, A_hi + aoff + kk * 32);
            ldm4(alo, A_lo + aoff + kk * 32);
            ldm4(b0h, B_hi + boff + kk * 32);
            ldm4(b1h, B_hi + boff + kk * 32 + 16);
            ldm4(b0l, B_lo + boff + kk * 32);
            ldm4(b1l, B_lo + boff + kk * 32 + 16);
#pragma unroll
            for (int q = 0; q < 4; ++q) mma16816(acc[q], ahi, b0h[q], b1h[q]);
#pragma unroll
            for (int q = 0; q < 4; ++q) mma16816(acc[q], alo, b0h[q], b1h[q]);
#pragma unroll
            for (int q = 0; q < 4; ++q) mma16816(acc[q], ahi, b0l[q], b1l[q]);
        }
        __syncthreads();
    }

    // write accs to smem gates (stride 68 f32)
    float* sg = (float*)(smem + SMX_GT);
    {
        const int dr = lane >> 2, dc = (lane & 3) * 2;
#pragma unroll
        for (int q = 0; q < 4; ++q) {
            const int col = wn * 32 + q * 8 + dc;
            *(float2*)&sg[(wm * 16 + dr)     * 68 + col] = make_float2(acc[q][0], acc[q][1]);
            *(float2*)&sg[(wm * 16 + dr + 8) * 68 + col] = make_float2(acc[q][2], acc[q][3]);
        }
    }
    __syncthreads();

    // bias + permuted scatter to g_xp (streaming stores): 128 tiles of 32 rows
    {
        const float* bih = d ? bih_b : bih_f;
        const float* bhh = d ? bhh_b : bhh_f;
        const int r = tid >> 2, jj = tid & 3;
        const int gr = gt * 64 + r;
        const float bias = bih[gr] + bhh[gr];
        const int v = gr >> 10, u = gr & 1023;
        const int mt = u >> 3, prow = v * 8 + (u & 7);
        float* dst = g_xp + (((size_t)(d * TSEQ + t) * 128 + mt) * 32 + prow) * 64 + jj * 16;
#pragma unroll
        for (int p = 0; p < 4; ++p) {
            float4 o = *(float4*)&sg[r * 68 + jj * 16 + p * 4];
            o.x += bias; o.y += bias; o.z += bias; o.w += bias;
            __stcs((float4*)(dst + p * 4), o);
        }
    }
}

// ---------------- one recurrent step: HMMA GEMM + fused pointwise ------------
// grid (128, 2): mt (32-row tiles), d.  256 threads = 8 warps (2M x 4N),
// warp tile 16x16.  2 CTAs co-resident per SM (smem 110.8KB).
// Staging via cp.async.bulk + mbarrier (elected thread). 4-slot ring, chunks
// in pairs, one __syncthreads per pair. xp in registers; gates alias slot 0.
__global__ __launch_bounds__(256, 2) void step_mma(int t)
{
    extern __shared__ __align__(16) unsigned char smem[];
    const uint32_t sb = smem_u32(smem);

    const int tid  = threadIdx.x;
    const int wid  = tid >> 5;
    const int lane = tid & 31;
    const int mt   = blockIdx.x;
    const int d    = blockIdx.y;
    const int pp   = t & 1;

    const unsigned char* srcA_hi = g_Wt + (((size_t)(d * 2 + 0) * 128 + mt) * NCHUNK) * CHA;
    const unsigned char* srcA_lo = g_Wt + (((size_t)(d * 2 + 1) * 128 + mt) * NCHUNK) * CHA;
    const unsigned char* srcB_hi = g_hT + (((size_t)(d * 2 + pp) * 2 + 0) * NCHUNK) * CHB;
    const unsigned char* srcB_lo = g_hT + (((size_t)(d * 2 + pp) * 2 + 1) * NCHUNK) * CHB;

    const uint32_t mb[2] = { sb + SM_MBAR, sb + SM_MBAR + 8 };

    // stage chunk-pair (c0, c0+1) into slots c0&3, (c0+1)&3, completing mbar
    auto stage_pair = [&](int c0, uint32_t mbar) {
        mbar_expect(mbar, 2 * (2 * CHA + 2 * CHB));
#pragma unroll
        for (int cc = c0; cc < c0 + 2; ++cc) {
            const int s = cc & 3;
            bulkcp(sb + s * SLOT + OFF_AHI, srcA_hi + (size_t)cc * CHA, CHA, mbar);
            bulkcp(sb + s * SLOT + OFF_ALO, srcA_lo + (size_t)cc * CHA, CHA, mbar);
            bulkcp(sb + s * SLOT + OFF_BHI, srcB_hi + (size_t)cc * CHB, CHB, mbar);
            bulkcp(sb + s * SLOT + OFF_BLO, srcB_lo + (size_t)cc * CHB, CHB, mbar);
        }
    };

    if (tid == 0) {
        mbar_init(mb[0], 1);
        mbar_init(mb[1], 1);
    }
    __syncthreads();
    if (tid == 0) {
        stage_pair(0, mb[0]);   // chunks 0,1 -> slots 0,1
        stage_pair(2, mb[1]);   // chunks 2,3 -> slots 2,3
    }

    // xp slice into registers (first 128 threads; latency hidden by staging)
    const int u  = tid >> 4;             // (tid<128) 0..7
    const int b0 = (tid & 15) * 4;
    float4 xv[4];
    if (tid < 128) {
        const float* xps = g_xp + (((size_t)(d * TSEQ + t) * 128 + mt) * 32) * 64;
#pragma unroll
        for (int v = 0; v < 4; ++v)
            xv[v] = __ldg((const float4*)(xps + (v * 8 + u) * 64 + b0));
    }

    const int wm = wid & 1;                  // M group (16 rows)
    const int wn = wid >> 1;                 // N group (16 cols)
    const int ti = lane >> 3, li = lane & 7;
    const uint32_t aoff  = (uint32_t)((wm * 16 + (ti & 1) * 8 + li) * STRD + (ti >> 1) * 16);
    const uint32_t boffA = (uint32_t)(((ti >> 1) * 8 + li) * STRD + (wn * 16 + (ti & 1) * 8) * 2);

    float acc[2][4];
#pragma unroll
    for (int q = 0; q < 2; ++q)
#pragma unroll
        for (int l = 0; l < 4; ++l) acc[q][l] = 0.0f;

#pragma unroll 1
    for (int p = 0; p < 8; ++p) {
        // wait pair p's data (chunks 2p, 2p+1)
        mbar_wait(mb[p & 1], (p >> 1) & 1);
#pragma unroll
        for (int h = 0; h < 2; ++h) {
            const int s = (2 * p + h) & 3;
            const uint32_t A_hi = sb + s * SLOT + OFF_AHI;
            const uint32_t A_lo = sb + s * SLOT + OFF_ALO;
            const uint32_t B_hi = sb + s * SLOT + OFF_BHI;
            const uint32_t B_lo = sb + s * SLOT + OFF_BLO;
#pragma unroll
            for (int kk = 0; kk < 4; ++kk) {
                uint32_t ahi[4], alo[4], bh[4], bl[4];
                ldm4(ahi, A_hi + aoff + kk * 32);
                ldm4(alo, A_lo + aoff + kk * 32);
                ldm4t(bh, B_hi + boffA + kk * 16 * STRD);
                ldm4t(bl, B_lo + boffA + kk * 16 * STRD);
                mma16816(acc[0], ahi, bh[0], bh[2]);
                mma16816(acc[1], ahi, bh[1], bh[3]);
                mma16816(acc[0], alo, bh[0], bh[2]);
                mma16816(acc[1], alo, bh[1], bh[3]);
                mma16816(acc[0], ahi, bl[0], bl[2]);
                mma16816(acc[1], ahi, bl[1], bl[3]);
            }
        }
        __syncthreads();   // all consumers done with pair p's slots
        if (p < 6 && tid == 0)
            stage_pair(2 * p + 4, mb[p & 1]);   // reuse pair p's slots
    }

    // write accs to smem gates (32 rows, stride 68 f32) — aliases slot 0
    float* sg = (float*)smem;
    {
        const int dr = lane >> 2, dc = (lane & 3) * 2;
#pragma unroll
        for (int q = 0; q < 2; ++q) {
            const int col = wn * 16 + q * 8 + dc;
            *(float2*)&sg[(wm * 16 + dr)     * 68 + col] = make_float2(acc[q][0], acc[q][1]);
            *(float2*)&sg[(wm * 16 + dr + 8) * 68 + col] = make_float2(acc[q][2], acc[q][3]);
        }
    }
    __syncthreads();

    // fused pointwise LSTM (first 128 threads; xp from registers)
    if (tid < 128) {
        float gv[4][4];
#pragma unroll
        for (int v = 0; v < 4; ++v) {
            const int r = v * 8 + u;
#pragma unroll
            for (int l = 0; l < 4; ++l)
                gv[v][l] = sg[r * 68 + b0 + l] + ((const float*)&xv[v])[l];
        }
        float* cp = g_c + (((size_t)d * 128 + mt) * 8 + u) * 64 + b0;
        float4 cv = *(float4*)cp;
        float* cl = (float*)&cv;
        float hv[4];
#pragma unroll
        for (int l = 0; l < 4; ++l) {
            float ig = sigmoidf_(gv[0][l]);
            float fg = sigmoidf_(gv[1][l]);
            float gg = tanhf(gv[2][l]);
            float og = sigmoidf_(gv[3][l]);
            float cn = fg * cl[l] + ig * gg;
            cl[l] = cn;
            hv[l] = og * tanhf(cn);
        }
        *(float4*)cp = cv;

        const int t_out = d ? (TSEQ - 1 - t) : t;
        const int ug = mt * 8 + u;
        __stcs((float4*)&g_hist[((size_t)(d * TSEQ + t_out) * HIDD + ug) * BATCH + b0],
               make_float4(hv[0], hv[1], hv[2], hv[3]));

        __nv_bfloat16 ph[4], plo[4];
#pragma unroll
        for (int l = 0; l < 4; ++l) {
            ph[l]  = __float2bfloat16(hv[l]);
            plo[l] = __float2bfloat16(hv[l] - __bfloat162float(ph[l]));
        }
        const int c = ug >> 6, kl = ug & 63;
        const size_t off = (size_t)c * CHB + (size_t)kl * STRD + b0 * 2;
        unsigned char* wb_hi = g_hT + (((size_t)(d * 2 + (pp ^ 1)) * 2 + 0) * NCHUNK) * CHB;
        unsigned char* wb_lo = g_hT + (((size_t)(d * 2 + (pp ^ 1)) * 2 + 1) * NCHUNK) * CHB;
        *(u64*)(wb_hi + off) = *(u64*)ph;
        *(u64*)(wb_lo + off) = *(u64*)plo;
    }
}

// ---------------- combine: out[b][t][h] = hf + hb ---------------------------
__global__ __launch_bounds__(256) void combine_kernel(float* __restrict__ out)
{
    __shared__ float s[128 * 65];
    const int uc  = blockIdx.x;
    const int t   = blockIdx.y;
    const int tid = threadIdx.x;
    const float* hf = g_hist + (size_t)t          * HIDD * BATCH;
    const float* hb = g_hist + (size_t)(TSEQ + t) * HIDD * BATCH;
    for (int x = tid; x < 128 * 64; x += 256) {
        int uu = x >> 6, b = x & 63;
        int u = uc * 128 + uu;
        s[uu * 65 + b] = hf[(size_t)u * BATCH + b] + hb[(size_t)u * BATCH + b];
    }
    __syncthreads();
    for (int x = tid; x < 128 * 64; x += 256) {
        int b = x >> 7, uu = x & 127;
        out[((size_t)b * TSEQ + t) * HIDD + uc * 128 + uu] = s[uu * 65 + b];
    }
}

// ---------------- launch -----------------------------------------------------
extern "C" void kernel_launch(void* const* d_in, const int* in_sizes, int n_in,
                              void* d_out, int out_size)
{
    const int*   src   = (const int*)  d_in[0];
    const float* emb   = (const float*)d_in[1];
    const float* Wih_f = (const float*)d_in[2];
    const float* Whh_f = (const float*)d_in[3];
    const float* bih_f = (const float*)d_in[4];
    const float* bhh_f = (const float*)d_in[5];
    const float* Wih_b = (const float*)d_in[6];
    const float* Whh_b = (const float*)d_in[7];
    const float* bih_b = (const float*)d_in[8];
    const float* bhh_b = (const float*)d_in[9];

    cudaFuncSetAttribute(step_mma, cudaFuncAttributeMaxDynamicSharedMemorySize, SMEM_STEP);
    cudaFuncSetAttribute(xproj_mma, cudaFuncAttributeMaxDynamicSharedMemorySize, SMEM_X);

    init_kernel<<<288, 1024>>>();
    prep_all<<<48384, 256>>>(Whh_f, Whh_b, Wih_f, Wih_b, emb);
    xproj_mma<<<dim3(64, 512, 2), 256, SMEM_X>>>(src, bih_f, bhh_f, bih_b, bhh_b);
    for (int t = 0; t < TSEQ; ++t)
        step_mma<<<dim3(128, 2), 256, SMEM_STEP>>>(t);
    combine_kernel<<<dim3(8, 512), 256>>>((float*)d_out);
}